// round 4
// baseline (speedup 1.0000x reference)
#include <cuda_runtime.h>
#include <cuda_bf16.h>
#include <cstdint>

#define T_DIM  128
#define B_DIM  64
#define IN_RAW 144
#define K0_PAD 192
#define NC0    3              // K0_PAD/64
#define NCH    32             // H_DIM/64
#define H_DIM  2048
#define C_DIM  10
#define BN_EPS 1e-5f
#define MTOT   (T_DIM*B_DIM)  // 8192
#define BH     (B_DIM*H_DIM)  // 131072

// GEMM tile config
#define BM 256
#define BN 128
#define KC 64
#define A_CHUNK 65536         // 256 rows x 128B x (hi+lo)
#define B_CHUNK 32768         // 128 rows x 128B x (hi+lo)
#define STAGE_BYTES (A_CHUNK + B_CHUNK)     // 98304
#define DSMEM_BYTES (2*STAGE_BYTES)         // 196608

// ---------------- scratch (allocation-free device globals) -----------------
// A-pack: [mblk(32)][kc(<=32)][hi 32KB][lo 32KB], SW128-swizzled rows of 128B
__device__ __align__(128) unsigned char g_apack[32u*32u*A_CHUNK];   // 64MB
// B-pack: [nblk(16)][kc(<=32)][hi 16KB][lo 16KB]
__device__ __align__(128) unsigned char g_bpack[16u*32u*B_CHUNK];   // 16MB
__device__ float g_z[MTOT*H_DIM];                                   // 64MB
__device__ float g_biasadj[H_DIM];
__device__ float g_psum[BH];
__device__ float g_psumsq[BH];
__device__ float g_scale[H_DIM];
__device__ float g_shift[H_DIM];
__device__ float g_hlast[BH];

// ---------------- PTX helpers ----------------
__device__ __forceinline__ uint32_t smem_u32(const void* p) {
    uint32_t a;
    asm("{ .reg .u64 t; cvta.to.shared.u64 t, %1; cvt.u32.u64 %0, t; }" : "=r"(a) : "l"(p));
    return a;
}
__device__ __forceinline__ void bulk_g2s(uint32_t dst, const void* src,
                                         uint32_t bytes, uint32_t mbar) {
    asm volatile(
        "cp.async.bulk.shared::cluster.global.mbarrier::complete_tx::bytes [%0], [%1], %2, [%3];"
        :: "r"(dst), "l"(src), "r"(bytes), "r"(mbar) : "memory");
}
#define MBAR_INIT(a, c) asm volatile("mbarrier.init.shared.b64 [%0], %1;" :: "r"(a), "r"(c) : "memory")
#define MBAR_EXPECT_TX(a, b) asm volatile("mbarrier.arrive.expect_tx.shared.b64 _, [%0], %1;" :: "r"(a), "r"(b) : "memory")
#define FENCE_ASYNC() asm volatile("fence.proxy.async.shared::cta;" ::: "memory")
#define MBAR_WAIT(a, ph) do { \
    uint32_t _done; \
    asm volatile("{\n\t.reg .pred p;\n\tmbarrier.try_wait.parity.acquire.cta.shared::cta.b64 p, [%1], %2;\n\tselp.b32 %0,1,0,p;\n\t}" \
        : "=r"(_done) : "r"(a), "r"(ph) : "memory"); \
    if (!_done) { \
        asm volatile("{\n\t.reg .pred P1;\n\tWL_%=:\n\tmbarrier.try_wait.parity.acquire.cta.shared::cta.b64 P1, [%0], %1, 0x989680;\n\t@P1 bra.uni WD_%=;\n\tbra.uni WL_%=;\n\tWD_%=:\n\t}" \
            :: "r"(a), "r"(ph) : "memory"); \
    } \
} while (0)

__device__ __forceinline__ void ldsm4(uint32_t r[4], uint32_t addr) {
    asm volatile("ldmatrix.sync.aligned.m8n8.x4.shared.b16 {%0,%1,%2,%3}, [%4];"
        : "=r"(r[0]), "=r"(r[1]), "=r"(r[2]), "=r"(r[3]) : "r"(addr));
}
__device__ __forceinline__ void mma16816(float c[4], const uint32_t a[4],
                                         uint32_t b0, uint32_t b1) {
    asm volatile(
        "mma.sync.aligned.m16n8k16.row.col.f32.bf16.bf16.f32 "
        "{%0,%1,%2,%3}, {%4,%5,%6,%7}, {%8,%9}, {%0,%1,%2,%3};"
        : "+f"(c[0]), "+f"(c[1]), "+f"(c[2]), "+f"(c[3])
        : "r"(a[0]), "r"(a[1]), "r"(a[2]), "r"(a[3]), "r"(b0), "r"(b1));
}

// split 8 fp32 -> 8 bf16 hi + 8 bf16 lo, two 16B stores
__device__ __forceinline__ void split_store8(unsigned char* hiDst, unsigned char* loDst,
                                             const float v[8]) {
    union { uint4 q; unsigned short us[8]; } Hq, Lq;
    #pragma unroll
    for (int i = 0; i < 8; ++i) {
        __nv_bfloat16 h = __float2bfloat16(v[i]);
        Hq.us[i] = __bfloat16_as_ushort(h);
        Lq.us[i] = __bfloat16_as_ushort(__float2bfloat16(v[i] - __bfloat162float(h)));
    }
    *reinterpret_cast<uint4*>(hiDst) = Hq.q;
    *reinterpret_cast<uint4*>(loDst) = Lq.q;
}
__device__ __forceinline__ uint32_t swz(uint32_t off) { return off ^ ((off >> 3) & 0x70); }

// ---------------- GEMM: Z = A@W^T + biasadj (3-product bf16 split) ---------
__global__ __launch_bounds__(256, 1)
void gemm_mma(const unsigned char* __restrict__ apack,
              const unsigned char* __restrict__ bpack,
              const float* __restrict__ biasadj, float* __restrict__ Z, int NC)
{
    extern __shared__ unsigned char dyn[];
    __shared__ __align__(8) uint64_t mbar_s[2];
    const uint32_t sb = smem_u32(dyn);
    const uint32_t mb = smem_u32(mbar_s);

    const int tid  = threadIdx.x;
    const int lane = tid & 31;
    const int wid  = tid >> 5;
    const int wm   = wid >> 1;            // 0..3  (m, 64 rows each)
    const int wn   = wid & 1;             // 0..1  (n, 64 cols each)
    const int nblk = blockIdx.x;
    const int mblk = blockIdx.y;

    const unsigned char* aSrc = apack + (size_t)mblk * NC * A_CHUNK;
    const unsigned char* bSrc = bpack + (size_t)nblk * NC * B_CHUNK;

    if (tid == 0) {
        MBAR_INIT(mb, 1);
        MBAR_INIT(mb + 8, 1);
        FENCE_ASYNC();
    }
    __syncthreads();
    if (tid == 0) {
        #pragma unroll
        for (int s = 0; s < 2; ++s) {
            MBAR_EXPECT_TX(mb + 8 * s, STAGE_BYTES);
            bulk_g2s(sb + s * STAGE_BYTES,           aSrc + (size_t)s * A_CHUNK, A_CHUNK, mb + 8 * s);
            bulk_g2s(sb + s * STAGE_BYTES + A_CHUNK, bSrc + (size_t)s * B_CHUNK, B_CHUNK, mb + 8 * s);
        }
    }

    // per-lane ldmatrix geometry (SW128)
    const int rowA  = wm * 64 + (lane & 15);
    const int rowB  = wn * 64 + ((lane >> 4) << 3) + (lane & 7);
    const int xorC  = (lane & 7) << 4;
    const int colA0 = (lane >> 4) * 16;
    const int colB0 = ((lane >> 3) & 1) * 16;

    float acc[4][8][4];
    #pragma unroll
    for (int i = 0; i < 4; ++i)
        #pragma unroll
        for (int j = 0; j < 8; ++j)
            #pragma unroll
            for (int q = 0; q < 4; ++q) acc[i][j][q] = 0.0f;

    int ph[2] = {0, 0};
    for (int c = 0; c < NC; ++c) {
        const int s = c & 1;
        MBAR_WAIT(mb + 8 * s, ph[s]);
        ph[s] ^= 1;
        const uint32_t st = sb + s * STAGE_BYTES;

        #pragma unroll
        for (int kk = 0; kk < 4; ++kk) {
            const uint32_t cA = (uint32_t)((kk * 32 + colA0) ^ xorC);
            const uint32_t cB = (uint32_t)((kk * 32 + colB0) ^ xorC);
            uint32_t ah[4][4], al[4][4];
            #pragma unroll
            for (int mi = 0; mi < 4; ++mi) {
                const uint32_t ra = (uint32_t)(rowA + mi * 16) * 128;
                ldsm4(ah[mi], st + ra + cA);
                ldsm4(al[mi], st + 32768 + ra + cA);
            }
            #pragma unroll
            for (int nj = 0; nj < 4; ++nj) {
                const uint32_t rb = (uint32_t)(rowB + nj * 16) * 128;
                uint32_t bh[4], bl[4];
                ldsm4(bh, st + 65536 + rb + cB);
                ldsm4(bl, st + 81920 + rb + cB);
                #pragma unroll
                for (int mi = 0; mi < 4; ++mi) {
                    mma16816(acc[mi][nj*2],   ah[mi], bh[0], bh[1]);
                    mma16816(acc[mi][nj*2+1], ah[mi], bh[2], bh[3]);
                    mma16816(acc[mi][nj*2],   ah[mi], bl[0], bl[1]);
                    mma16816(acc[mi][nj*2+1], ah[mi], bl[2], bl[3]);
                    mma16816(acc[mi][nj*2],   al[mi], bh[0], bh[1]);
                    mma16816(acc[mi][nj*2+1], al[mi], bh[2], bh[3]);
                }
            }
        }
        __syncthreads();
        if (c + 2 < NC && tid == 0) {
            MBAR_EXPECT_TX(mb + 8 * s, STAGE_BYTES);
            bulk_g2s(st,           aSrc + (size_t)(c + 2) * A_CHUNK, A_CHUNK, mb + 8 * s);
            bulk_g2s(st + A_CHUNK, bSrc + (size_t)(c + 2) * B_CHUNK, B_CHUNK, mb + 8 * s);
        }
    }

    // epilogue: + bias, write fp32 Z
    const int g  = lane >> 2;
    const int tg = lane & 3;
    #pragma unroll
    for (int mi = 0; mi < 4; ++mi) {
        const int r0 = mblk * BM + wm * 64 + mi * 16 + g;
        #pragma unroll
        for (int ni = 0; ni < 8; ++ni) {
            const int n = nblk * BN + wn * 64 + ni * 8 + tg * 2;
            const float2 bia = *reinterpret_cast<const float2*>(&biasadj[n]);
            float2 v0 = {acc[mi][ni][0] + bia.x, acc[mi][ni][1] + bia.y};
            float2 v1 = {acc[mi][ni][2] + bia.x, acc[mi][ni][3] + bia.y};
            *reinterpret_cast<float2*>(&Z[(size_t)r0 * H_DIM + n])       = v0;
            *reinterpret_cast<float2*>(&Z[(size_t)(r0 + 8) * H_DIM + n]) = v1;
        }
    }
}

// ---------------- x -> packed split A (layer 0, K padded to 192) -----------
__global__ __launch_bounds__(256)
void split_x(const float* __restrict__ x, unsigned char* __restrict__ apack)
{
    const int idx = blockIdx.x * 256 + threadIdx.x;   // MTOT*24 granules
    const int m  = idx / 24;
    const int k0 = (idx % 24) * 8;
    float v[8];
    if (k0 < IN_RAW) {
        const float4 a = *reinterpret_cast<const float4*>(&x[(size_t)m * IN_RAW + k0]);
        const float4 b = *reinterpret_cast<const float4*>(&x[(size_t)m * IN_RAW + k0 + 4]);
        v[0]=a.x; v[1]=a.y; v[2]=a.z; v[3]=a.w; v[4]=b.x; v[5]=b.y; v[6]=b.z; v[7]=b.w;
    } else {
        #pragma unroll
        for (int i = 0; i < 8; ++i) v[i] = 0.0f;
    }
    const int mblkr = m >> 8, row = m & 255, kc = k0 >> 6;
    const uint32_t off = swz((uint32_t)(row * 128 + (k0 & 63) * 2));
    unsigned char* d = apack + (size_t)(mblkr * NC0 + kc) * A_CHUNK + off;
    split_store8(d, d + 32768, v);
}

// ---------------- layer-0 weights -> packed B ------------------------------
__global__ __launch_bounds__(32)
void prep_w0(const float* __restrict__ W0, const float* __restrict__ b0,
             unsigned char* __restrict__ bpack, float* __restrict__ biasadj)
{
    const int n = blockIdx.x;
    const int gIdx = threadIdx.x;     // 0..31, use < 24
    if (gIdx < 24) {
        const int k0 = gIdx * 8;
        float v[8];
        if (k0 < IN_RAW) {
            const float4 a = *reinterpret_cast<const float4*>(&W0[(size_t)n * IN_RAW + k0]);
            const float4 b = *reinterpret_cast<const float4*>(&W0[(size_t)n * IN_RAW + k0 + 4]);
            v[0]=a.x; v[1]=a.y; v[2]=a.z; v[3]=a.w; v[4]=b.x; v[5]=b.y; v[6]=b.z; v[7]=b.w;
        } else {
            #pragma unroll
            for (int i = 0; i < 8; ++i) v[i] = 0.0f;
        }
        const int nblkr = n >> 7, row = n & 127, kc = k0 >> 6;
        const uint32_t off = swz((uint32_t)(row * 128 + (k0 & 63) * 2));
        unsigned char* d = bpack + (size_t)(nblkr * NC0 + kc) * B_CHUNK + off;
        split_store8(d, d + 16384, v);
    }
    if (gIdx == 0) biasadj[n] = b0[n];
}

// ---------------- layer l>=1 weights: fold BN, pack ------------------------
__global__ __launch_bounds__(256)
void prep_w(const float* __restrict__ W, const float* __restrict__ scale,
            const float* __restrict__ shift, const float* __restrict__ bias_in,
            unsigned char* __restrict__ bpack, float* __restrict__ biasadj)
{
    const int n = blockIdx.x;
    const int tid = threadIdx.x;
    const int k0 = tid * 8;
    __shared__ float red[256];

    const float* wrow = W + (size_t)n * H_DIM + k0;
    float w[8], v[8];
    *reinterpret_cast<float4*>(&w[0]) = *reinterpret_cast<const float4*>(wrow);
    *reinterpret_cast<float4*>(&w[4]) = *reinterpret_cast<const float4*>(wrow + 4);
    float sc[8], sh[8];
    *reinterpret_cast<float4*>(&sc[0]) = *reinterpret_cast<const float4*>(&scale[k0]);
    *reinterpret_cast<float4*>(&sc[4]) = *reinterpret_cast<const float4*>(&scale[k0 + 4]);
    *reinterpret_cast<float4*>(&sh[0]) = *reinterpret_cast<const float4*>(&shift[k0]);
    *reinterpret_cast<float4*>(&sh[4]) = *reinterpret_cast<const float4*>(&shift[k0 + 4]);

    float s = 0.0f;
    #pragma unroll
    for (int i = 0; i < 8; ++i) {
        v[i] = w[i] * sc[i];
        s = fmaf(sh[i], w[i], s);
    }
    const int nblkr = n >> 7, row = n & 127, kc = k0 >> 6;
    const uint32_t off = swz((uint32_t)(row * 128 + (k0 & 63) * 2));
    unsigned char* d = bpack + (size_t)(nblkr * NCH + kc) * B_CHUNK + off;
    split_store8(d, d + 16384, v);

    red[tid] = s;
    __syncthreads();
    for (int o = 128; o > 0; o >>= 1) {
        if (tid < o) red[tid] += red[tid + o];
        __syncthreads();
    }
    if (tid == 0) biasadj[n] = bias_in[n] + red[0];
}

// ---------------- IndRNN scan -> packed split A + stats --------------------
__global__ __launch_bounds__(256)
void scan_kernel(const float* __restrict__ Z, const float* __restrict__ u,
                 unsigned char* __restrict__ apack, float* __restrict__ hlast,
                 float* __restrict__ psum, float* __restrict__ psumsq)
{
    const int gIdx = blockIdx.x * 256 + threadIdx.x;   // 0..16383
    const int b  = gIdx >> 8;
    const int h0 = (gIdx & 255) * 8;
    const int j0 = b * H_DIM + h0;
    const int kc = h0 >> 6;
    const uint32_t cb = (uint32_t)((h0 & 63) * 2);

    float uh[8];
    *reinterpret_cast<float4*>(&uh[0]) = *reinterpret_cast<const float4*>(&u[h0]);
    *reinterpret_cast<float4*>(&uh[4]) = *reinterpret_cast<const float4*>(&u[h0 + 4]);

    float hc[8], s[8], s2[8];
    #pragma unroll
    for (int i = 0; i < 8; ++i) { hc[i] = 0.0f; s[i] = 0.0f; s2[i] = 0.0f; }

    for (int t = 0; t < T_DIM; ++t) {
        float zv[8];
        const float* zp = Z + (size_t)t * BH + j0;
        *reinterpret_cast<float4*>(&zv[0]) = *reinterpret_cast<const float4*>(zp);
        *reinterpret_cast<float4*>(&zv[4]) = *reinterpret_cast<const float4*>(zp + 4);
        #pragma unroll
        for (int i = 0; i < 8; ++i) {
            hc[i] = fmaxf(fmaf(uh[i], hc[i], zv[i]), 0.0f);
            s[i] += hc[i];
            s2[i] = fmaf(hc[i], hc[i], s2[i]);
        }
        const int m = t * B_DIM + b;
        const int mblkr = m >> 8, row = m & 255;
        const uint32_t off = swz((uint32_t)(row * 128) + cb);
        unsigned char* d = apack + (size_t)(mblkr * NCH + kc) * A_CHUNK + off;
        split_store8(d, d + 32768, hc);
    }
    *reinterpret_cast<float4*>(&hlast[j0])      = *reinterpret_cast<float4*>(&hc[0]);
    *reinterpret_cast<float4*>(&hlast[j0 + 4])  = *reinterpret_cast<float4*>(&hc[4]);
    *reinterpret_cast<float4*>(&psum[j0])       = *reinterpret_cast<float4*>(&s[0]);
    *reinterpret_cast<float4*>(&psum[j0 + 4])   = *reinterpret_cast<float4*>(&s[4]);
    *reinterpret_cast<float4*>(&psumsq[j0])     = *reinterpret_cast<float4*>(&s2[0]);
    *reinterpret_cast<float4*>(&psumsq[j0 + 4]) = *reinterpret_cast<float4*>(&s2[4]);
}

// ---------------- BN stats -> folded affine --------------------------------
__global__ __launch_bounds__(256)
void bn_finalize(const float* __restrict__ psum, const float* __restrict__ psumsq,
                 const float* __restrict__ gamma, const float* __restrict__ beta,
                 float* __restrict__ scale, float* __restrict__ shift)
{
    const int h = blockIdx.x * 256 + threadIdx.x;
    float s = 0.0f, s2 = 0.0f;
    #pragma unroll 8
    for (int b = 0; b < B_DIM; ++b) {
        s  += psum[b * H_DIM + h];
        s2 += psumsq[b * H_DIM + h];
    }
    const float inv_n = 1.0f / (float)(T_DIM * B_DIM);
    const float mean  = s * inv_n;
    const float var   = s2 * inv_n - mean * mean;
    const float rstd  = rsqrtf(var + BN_EPS);
    const float sc    = gamma[h] * rstd;
    scale[h] = sc;
    shift[h] = fmaf(-mean, sc, beta[h]);
}

// ---------------- final projection -----------------------------------------
__global__ __launch_bounds__(256)
void final_proj(const float* __restrict__ Hlast,
                const float* __restrict__ scale, const float* __restrict__ shift,
                const float* __restrict__ Wl, const float* __restrict__ bl,
                float* __restrict__ out)
{
    const int b = blockIdx.x, c = blockIdx.y;
    __shared__ float red[256];
    float s = 0.0f;
    for (int h = threadIdx.x; h < H_DIM; h += 256) {
        const float hn = fmaf(Hlast[b * H_DIM + h], scale[h], shift[h]);
        s = fmaf(hn, Wl[c * H_DIM + h], s);
    }
    red[threadIdx.x] = s;
    __syncthreads();
    for (int o = 128; o > 0; o >>= 1) {
        if (threadIdx.x < o) red[threadIdx.x] += red[threadIdx.x + o];
        __syncthreads();
    }
    if (threadIdx.x == 0) out[b * C_DIM + c] = red[0] + bl[c];
}

// ---------------- launcher --------------------------------------------------
extern "C" void kernel_launch(void* const* d_in, const int* in_sizes, int n_in,
                              void* d_out, int out_size)
{
    const float* x      = (const float*)d_in[0];
    const float* W0     = (const float*)d_in[1];
    const float* Ws     = (const float*)d_in[2];
    const float* bs     = (const float*)d_in[3];
    const float* us     = (const float*)d_in[4];
    const float* gammas = (const float*)d_in[5];
    const float* betas  = (const float*)d_in[6];
    const float* Wlast  = (const float*)d_in[7];
    const float* blast  = (const float*)d_in[8];
    float* out = (float*)d_out;

    unsigned char *apack, *bpack;
    float *z, *biasadj, *psum, *psumsq, *scale, *shift, *hlast;
    cudaGetSymbolAddress((void**)&apack,   g_apack);
    cudaGetSymbolAddress((void**)&bpack,   g_bpack);
    cudaGetSymbolAddress((void**)&z,       g_z);
    cudaGetSymbolAddress((void**)&biasadj, g_biasadj);
    cudaGetSymbolAddress((void**)&psum,    g_psum);
    cudaGetSymbolAddress((void**)&psumsq,  g_psumsq);
    cudaGetSymbolAddress((void**)&scale,   g_scale);
    cudaGetSymbolAddress((void**)&shift,   g_shift);
    cudaGetSymbolAddress((void**)&hlast,   g_hlast);

    cudaFuncSetAttribute(gemm_mma, cudaFuncAttributeMaxDynamicSharedMemorySize, DSMEM_BYTES);

    const dim3 ggrid(H_DIM / BN, MTOT / BM);   // 16 x 32

    // ---- layer 0 ----
    split_x<<<(MTOT * 24) / 256, 256>>>(x, apack);
    prep_w0<<<H_DIM, 32>>>(W0, bs, bpack, biasadj);
    gemm_mma<<<ggrid, 256, DSMEM_BYTES>>>(apack, bpack, biasadj, z, NC0);
    scan_kernel<<<(BH / 8) / 256, 256>>>(z, us, apack, hlast, psum, psumsq);
    bn_finalize<<<H_DIM / 256, 256>>>(psum, psumsq, gammas, betas, scale, shift);

    // ---- layers 1..3 ----
    for (int l = 1; l < 4; ++l) {
        prep_w<<<H_DIM, 256>>>(Ws + (size_t)(l - 1) * H_DIM * H_DIM, scale, shift,
                               bs + l * H_DIM, bpack, biasadj);
        gemm_mma<<<ggrid, 256, DSMEM_BYTES>>>(apack, bpack, biasadj, z, NCH);
        scan_kernel<<<(BH / 8) / 256, 256>>>(z, us + l * H_DIM, apack, hlast, psum, psumsq);
        bn_finalize<<<H_DIM / 256, 256>>>(psum, psumsq, gammas + l * H_DIM,
                                          betas + l * H_DIM, scale, shift);
    }

    final_proj<<<dim3(B_DIM, C_DIM), 256>>>(hlast, scale, shift, Wlast, blast, out);
}